// round 11
// baseline (speedup 1.0000x reference)
#include <cuda_runtime.h>
#include <cuda_fp16.h>
#include <cstdint>
#include <math.h>

// Problem dims (fixed by the dataset)
#define B_ 4
#define S_ 4096
#define D_ 2048
#define DI_ 8192
#define MTOT (B_ * S_)   // 16384

// ---------------------------------------------------------------------------
// Static device scratch
// ---------------------------------------------------------------------------
__device__ __half g_xh[(size_t)MTOT * D_];    //  64 MB  x in fp16
__device__ __half g_wuph[(size_t)DI_ * D_];   //  32 MB  w_up fp16 [DI, D] K-major
__device__ __half g_wdh[(size_t)D_ * DI_];    //  32 MB  w_down fp16 [D, DI] K-major
__device__ __half g_h[(size_t)MTOT * DI_];    // 256 MB  gelu(up) intermediate

// ---------------------------------------------------------------------------
// GEMM config: CTA 128x128, 4 warps (2M x 2N), warp tile 64x64, BK=64,
// 3 stages (96 KB), 2 CTAs/SM. PERSISTENT CTAs: the chunk pipeline runs
// continuously across output tiles (refill slots of the last two k-iters
// fetch the next tile's chunks 0,1; epilogue overlaps those loads).
// ---------------------------------------------------------------------------
constexpr int BM = 128;
constexpr int BN = 128;
constexpr int BK = 64;
constexpr int STAGES = 3;
constexpr int NTHREADS = 128;
constexpr int A_CHUNKS = BM * 8;
constexpr int B_CHUNKS = BN * 8;
constexpr int STAGE_CHUNKS = A_CHUNKS + B_CHUNKS;
constexpr int STAGE_BYTES = (BM + BN) * 128;     // 32 KB
constexpr int SMEM_BYTES = STAGES * STAGE_BYTES; // 96 KB

// ---------------------------------------------------------------------------
// PTX helpers
// ---------------------------------------------------------------------------
__device__ __forceinline__ uint32_t smem_u32(const void* p) {
    return (uint32_t)__cvta_generic_to_shared(p);
}
__device__ __forceinline__ void cp_async16(uint32_t dst, const void* src) {
    asm volatile("cp.async.cg.shared.global [%0], [%1], 16;\n"
                 :: "r"(dst), "l"(src) : "memory");
}
__device__ __forceinline__ void cp_commit() {
    asm volatile("cp.async.commit_group;\n" ::: "memory");
}
template <int N>
__device__ __forceinline__ void cp_wait() {
    asm volatile("cp.async.wait_group %0;\n" :: "n"(N) : "memory");
}
__device__ __forceinline__ void ldsm_x4(uint32_t& r0, uint32_t& r1, uint32_t& r2,
                                        uint32_t& r3, uint32_t addr) {
    asm volatile("ldmatrix.sync.aligned.m8n8.x4.shared.b16 {%0,%1,%2,%3}, [%4];\n"
                 : "=r"(r0), "=r"(r1), "=r"(r2), "=r"(r3) : "r"(addr));
}
__device__ __forceinline__ void mma16816(float* d, const uint32_t* a, const uint32_t* b) {
    asm volatile(
        "mma.sync.aligned.m16n8k16.row.col.f32.f16.f16.f32 "
        "{%0,%1,%2,%3}, {%4,%5,%6,%7}, {%8,%9}, {%0,%1,%2,%3};\n"
        : "+f"(d[0]), "+f"(d[1]), "+f"(d[2]), "+f"(d[3])
        : "r"(a[0]), "r"(a[1]), "r"(a[2]), "r"(a[3]), "r"(b[0]), "r"(b[1]));
}
__device__ __forceinline__ float gelu_exact(float v) {
    return 0.5f * v * (1.0f + erff(v * 0.70710678118654752f));
}

// ---------------------------------------------------------------------------
// Conversion kernels
// ---------------------------------------------------------------------------
__global__ void cvt_x_kernel(const float* __restrict__ in) {
    int i = blockIdx.x * blockDim.x + threadIdx.x;
    float4 v = reinterpret_cast<const float4*>(in)[i];
    __half2* o = reinterpret_cast<__half2*>(g_xh);
    o[2 * i]     = __floats2half2_rn(v.x, v.y);
    o[2 * i + 1] = __floats2half2_rn(v.z, v.w);
}
__global__ void cvt_wup_kernel(const float* __restrict__ in) {
    int i = blockIdx.x * blockDim.x + threadIdx.x;
    float4 v = reinterpret_cast<const float4*>(in)[i];
    __half2* o = reinterpret_cast<__half2*>(g_wuph);
    o[2 * i]     = __floats2half2_rn(v.x, v.y);
    o[2 * i + 1] = __floats2half2_rn(v.z, v.w);
}
__global__ void cvt_wd_kernel(const int* __restrict__ in) {
    int i = blockIdx.x * blockDim.x + threadIdx.x;
    int4 v = reinterpret_cast<const int4*>(in)[i];
    __half2* o = reinterpret_cast<__half2*>(g_wdh);
    o[2 * i]     = __floats2half2_rn((float)v.x, (float)v.y);
    o[2 * i + 1] = __floats2half2_rn((float)v.z, (float)v.w);
}

// ---------------------------------------------------------------------------
// Persistent tiled fp16 GEMM, fused epilogue, continuous chunk pipeline.
// Tile t -> (m = t / (NDIM/BN), n = t % (NDIM/BN)); t advances by gridDim.x.
// Per k-iter body identical to round-10; refill target rolls over into the
// next tile's chunks 0,1 during the last two k-iters.
// ---------------------------------------------------------------------------
template <int KDIM, int NDIM, bool IS_GEMM1>
__global__ void __launch_bounds__(NTHREADS, 2)
ffn_gemm_kernel(const float* __restrict__ bias,
                const float* __restrict__ scale,
                float* __restrict__ outp,
                int ntiles)
{
    extern __shared__ uint4 smem[];   // [STAGES][(BM+BN)*8] 16B chunks

    const __half* Ag = IS_GEMM1 ? g_xh   : g_h;
    const __half* Bg = IS_GEMM1 ? g_wuph : g_wdh;

    constexpr int NT = NDIM / BN;
    constexpr int KTILES = KDIM / BK;

    const int tid = threadIdx.x;
    const int wid = tid >> 5;
    const int lane = tid & 31;
    const int wm = (wid & 1) * 64;
    const int wn = (wid >> 1) * 64;

    // ---- Hoisted per-thread load addressing ----
    const int rBase = tid >> 3;                  // row within tile, +16 per iter
    const int cIdx  = tid & 7;                   // 16B chunk column
    const int cSw   = cIdx ^ (rBase & 7);        // swizzled col (row-invariant +16)
    const int dstBase = rBase * 8 + cSw;

    // Load one BK-chunk (A+B) of tile t into stage s.
    auto load_chunk = [&](int s, int t, int kt) {
        const int m0 = (t / NT) * BM;
        const int n0 = (t % NT) * BN;
        const __half* aS = Ag + (size_t)(m0 + rBase) * KDIM + cIdx * 8 + kt * BK;
        const __half* bS = Bg + (size_t)(n0 + rBase) * KDIM + cIdx * 8 + kt * BK;
        uint4* Ad = smem + s * STAGE_CHUNKS + dstBase;
        uint4* Bd = Ad + A_CHUNKS;
#pragma unroll
        for (int i = 0; i < A_CHUNKS / NTHREADS; ++i)    // 8 iters
            cp_async16(smem_u32(Ad + i * 128), aS + (size_t)i * 16 * KDIM);
#pragma unroll
        for (int i = 0; i < B_CHUNKS / NTHREADS; ++i)    // 8 iters
            cp_async16(smem_u32(Bd + i * 128), bS + (size_t)i * 16 * KDIM);
    };

    // Fixed per-thread LDSM indices
    const int rowA0 = wm + (lane & 15);
    const int rowB0 = wn + ((lane >> 4) << 3) + (lane & 7);
    const int cA = (lane >> 4);
    const int cB = ((lane >> 3) & 1);

    uint32_t fA[2][4][4];
    uint32_t fB[2][4][4];

    auto ldsm_kk = [&](const uint4* Aa, const uint4* Ba, int kk, int buf) {
#pragma unroll
        for (int mt = 0; mt < 4; ++mt) {
            int row = rowA0 + mt * 16;
            int c = kk * 2 + cA;
            ldsm_x4(fA[buf][mt][0], fA[buf][mt][1], fA[buf][mt][2], fA[buf][mt][3],
                    smem_u32(Aa + row * 8 + (c ^ (row & 7))));
        }
#pragma unroll
        for (int nt2 = 0; nt2 < 4; ++nt2) {
            int row = rowB0 + nt2 * 16;
            int c = kk * 2 + cB;
            ldsm_x4(fB[buf][nt2][0], fB[buf][nt2][1], fB[buf][nt2][2], fB[buf][nt2][3],
                    smem_u32(Ba + row * 8 + (c ^ (row & 7))));
        }
    };

    float acc[4][8][4];

    auto mma_kk = [&](int buf) {
#pragma unroll
        for (int mt = 0; mt < 4; ++mt)
#pragma unroll
            for (int nt = 0; nt < 8; ++nt)
                mma16816(acc[mt][nt], fA[buf][mt], &fB[buf][nt >> 1][(nt & 1) * 2]);
    };

    int t = blockIdx.x;
    if (t >= ntiles) return;

    // Prime the pipeline: chunks 0,1 of first tile into stages 0,1.
    load_chunk(0, t, 0);
    cp_commit();
    load_chunk(1, t, 1);
    cp_commit();
    cp_wait<STAGES - 2>();   // chunk 0 done (own group)
    __syncthreads();         // published

    int cur = 0;             // stage of the chunk about to be consumed

    for (; t < ntiles; t += gridDim.x) {
        const int t_next = t + gridDim.x;
        const bool has_next = (t_next < ntiles);

#pragma unroll
        for (int mt = 0; mt < 4; ++mt)
#pragma unroll
            for (int nt = 0; nt < 8; ++nt)
#pragma unroll
                for (int i = 0; i < 4; ++i) acc[mt][nt][i] = 0.0f;

        // kk=0 fragments of this tile (stage `cur`, published by last bar).
        {
            const uint4* Aa = smem + cur * STAGE_CHUNKS;
            ldsm_kk(Aa, Aa + A_CHUNKS, 0, 0);
        }

        for (int kt = 0; kt < KTILES; ++kt) {
            const uint4* Aa = smem + cur * STAGE_CHUNKS;
            const uint4* Ba = Aa + A_CHUNKS;
            const int nxt = (cur == 2) ? 0 : cur + 1;      // stage of chunk kt+1
            const int lst = (cur == 0) ? 2 : cur - 1;      // stage for chunk kt+2

            // Refill: chunk kt+2 of this tile, or chunks 0,1 of the next tile.
            int lk = kt + 2;
            if (lk < KTILES) load_chunk(lst, t, lk);
            else if (has_next) load_chunk(lst, t_next, lk - KTILES);
            cp_commit();   // unconditional: uniform group count

            ldsm_kk(Aa, Ba, 1, 1); mma_kk(0);
            ldsm_kk(Aa, Ba, 2, 0); mma_kk(1);
            ldsm_kk(Aa, Ba, 3, 1); mma_kk(0);

            cp_wait<STAGES - 2>();   // chunk kt+1 group done
            __syncthreads();         // published; frees stage `lst` refilled next iter
            if (kt + 1 < KTILES) {
                const uint4* An = smem + nxt * STAGE_CHUNKS;
                ldsm_kk(An, An + A_CHUNKS, 0, 0);   // prefetch next chunk kk=0
            }
            mma_kk(1);               // independent of the prefetch

            cur = nxt;
        }

        // ---- epilogue (next tile's chunks 0,1 already in flight) ----
        const int m0 = (t / NT) * BM;
        const int n0 = (t % NT) * BN;
        const int r0g = m0 + wm + (lane >> 2);
        const int c0g = n0 + wn + ((lane & 3) << 1);

        if (IS_GEMM1) {
#pragma unroll
            for (int mt = 0; mt < 4; ++mt)
#pragma unroll
                for (int hrow = 0; hrow < 2; ++hrow) {
                    int row = r0g + mt * 16 + hrow * 8;
#pragma unroll
                    for (int nt = 0; nt < 8; ++nt) {
                        int col = c0g + nt * 8;
                        float v0 = acc[mt][nt][hrow * 2]     + bias[col];
                        float v1 = acc[mt][nt][hrow * 2 + 1] + bias[col + 1];
                        v0 = gelu_exact(v0);
                        v1 = gelu_exact(v1);
                        *reinterpret_cast<__half2*>(&g_h[(size_t)row * NDIM + col]) =
                            __floats2half2_rn(v0, v1);
                    }
                }
        } else {
#pragma unroll
            for (int mt = 0; mt < 4; ++mt)
#pragma unroll
                for (int hrow = 0; hrow < 2; ++hrow) {
                    int row = r0g + mt * 16 + hrow * 8;
#pragma unroll
                    for (int nt = 0; nt < 8; ++nt) {
                        int col = c0g + nt * 8;
                        float2 o;
                        o.x = acc[mt][nt][hrow * 2]     * scale[col]     + bias[col];
                        o.y = acc[mt][nt][hrow * 2 + 1] * scale[col + 1] + bias[col + 1];
                        *reinterpret_cast<float2*>(&outp[(size_t)row * NDIM + col]) = o;
                    }
                }
        }
    }
}

// ---------------------------------------------------------------------------
// Launch
// ---------------------------------------------------------------------------
extern "C" void kernel_launch(void* const* d_in, const int* in_sizes, int n_in,
                              void* d_out, int out_size)
{
    const float* x            = (const float*)d_in[0];  // [B,S,D]
    const float* w_up         = (const float*)d_in[1];  // [DI,D]
    const float* b_up         = (const float*)d_in[2];  // [DI]
    const int*   w_down_q     = (const int*)  d_in[3];  // [D,DI] int32
    const float* w_down_scale = (const float*)d_in[4];  // [D]
    const float* b_down       = (const float*)d_in[5];  // [D]
    float* out = (float*)d_out;                         // [B,S,D]

    cvt_x_kernel  <<<(MTOT * D_) / 4 / 256, 256>>>(x);
    cvt_wup_kernel<<<(DI_ * D_) / 4 / 256, 256>>>(w_up);
    cvt_wd_kernel <<<(D_ * DI_) / 4 / 256, 256>>>(w_down_q);

    int smCount = 148;
    cudaDeviceGetAttribute(&smCount, cudaDevAttrMultiProcessorCount, 0);

    const int ntiles1 = (DI_ / BN) * (MTOT / BM);   // 8192
    const int ntiles2 = (D_ / BN) * (MTOT / BM);    // 2048
    int grid1 = 2 * smCount; if (grid1 > ntiles1) grid1 = ntiles1;
    int grid2 = 2 * smCount; if (grid2 > ntiles2) grid2 = ntiles2;

    cudaFuncSetAttribute(ffn_gemm_kernel<D_, DI_, true>,
                         cudaFuncAttributeMaxDynamicSharedMemorySize, SMEM_BYTES);
    ffn_gemm_kernel<D_, DI_, true>
        <<<grid1, NTHREADS, SMEM_BYTES>>>(b_up, nullptr, nullptr, ntiles1);

    cudaFuncSetAttribute(ffn_gemm_kernel<DI_, D_, false>,
                         cudaFuncAttributeMaxDynamicSharedMemorySize, SMEM_BYTES);
    ffn_gemm_kernel<DI_, D_, false>
        <<<grid2, NTHREADS, SMEM_BYTES>>>(b_down, w_down_scale, out, ntiles2);
}

// round 12
// speedup vs baseline: 1.0621x; 1.0621x over previous
#include <cuda_runtime.h>
#include <cuda_fp16.h>
#include <cstdint>
#include <math.h>

// Problem dims (fixed by the dataset)
#define B_ 4
#define S_ 4096
#define D_ 2048
#define DI_ 8192
#define MTOT (B_ * S_)   // 16384

// ---------------------------------------------------------------------------
// Static device scratch
// ---------------------------------------------------------------------------
__device__ __half g_xh[(size_t)MTOT * D_];    //  64 MB  x in fp16
__device__ __half g_wuph[(size_t)DI_ * D_];   //  32 MB  w_up fp16 [DI, D] K-major
__device__ __half g_wdh[(size_t)D_ * DI_];    //  32 MB  w_down fp16 [D, DI] K-major
__device__ __half g_h[(size_t)MTOT * DI_];    // 256 MB  gelu(up) intermediate

// ---------------------------------------------------------------------------
// GEMM config: CTA 128x128, 4 warps (2M x 2N), warp tile 64x64, BK=64,
// 3 stages (96 KB), 2 CTAs/SM. Round-10 structure (best known): fragment
// double buffering + cross-tile ldsm prefetch + hoisted load addressing.
// This round: smem-resident bias/scale for the epilogue; fused conversions.
// ---------------------------------------------------------------------------
constexpr int BM = 128;
constexpr int BN = 128;
constexpr int BK = 64;
constexpr int STAGES = 3;
constexpr int NTHREADS = 128;
constexpr int A_CHUNKS = BM * 8;
constexpr int B_CHUNKS = BN * 8;
constexpr int STAGE_CHUNKS = A_CHUNKS + B_CHUNKS;
constexpr int STAGE_BYTES = (BM + BN) * 128;     // 32 KB
constexpr int SMEM_BYTES = STAGES * STAGE_BYTES; // 96 KB dynamic

// ---------------------------------------------------------------------------
// PTX helpers
// ---------------------------------------------------------------------------
__device__ __forceinline__ uint32_t smem_u32(const void* p) {
    return (uint32_t)__cvta_generic_to_shared(p);
}
__device__ __forceinline__ void cp_async16(uint32_t dst, const void* src) {
    asm volatile("cp.async.cg.shared.global [%0], [%1], 16;\n"
                 :: "r"(dst), "l"(src) : "memory");
}
__device__ __forceinline__ void cp_commit() {
    asm volatile("cp.async.commit_group;\n" ::: "memory");
}
template <int N>
__device__ __forceinline__ void cp_wait() {
    asm volatile("cp.async.wait_group %0;\n" :: "n"(N) : "memory");
}
__device__ __forceinline__ void ldsm_x4(uint32_t& r0, uint32_t& r1, uint32_t& r2,
                                        uint32_t& r3, uint32_t addr) {
    asm volatile("ldmatrix.sync.aligned.m8n8.x4.shared.b16 {%0,%1,%2,%3}, [%4];\n"
                 : "=r"(r0), "=r"(r1), "=r"(r2), "=r"(r3) : "r"(addr));
}
__device__ __forceinline__ void mma16816(float* d, const uint32_t* a, const uint32_t* b) {
    asm volatile(
        "mma.sync.aligned.m16n8k16.row.col.f32.f16.f16.f32 "
        "{%0,%1,%2,%3}, {%4,%5,%6,%7}, {%8,%9}, {%0,%1,%2,%3};\n"
        : "+f"(d[0]), "+f"(d[1]), "+f"(d[2]), "+f"(d[3])
        : "r"(a[0]), "r"(a[1]), "r"(a[2]), "r"(a[3]), "r"(b[0]), "r"(b[1]));
}
__device__ __forceinline__ float gelu_exact(float v) {
    return 0.5f * v * (1.0f + erff(v * 0.70710678118654752f));
}

// ---------------------------------------------------------------------------
// Fused conversion kernel: one launch covers x, w_up, w_down_q.
// Block index ranges select the source; each thread converts 4 elements.
// ---------------------------------------------------------------------------
constexpr int XV   = (MTOT * D_) / 4;    // 8M float4 groups
constexpr int WUPV = (DI_ * D_) / 4;     // 4M
constexpr int WDV  = (D_ * DI_) / 4;     // 4M
constexpr int XB   = XV / 256;
constexpr int WUPB = WUPV / 256;
constexpr int WDB  = WDV / 256;

__global__ void cvt_all_kernel(const float* __restrict__ x,
                               const float* __restrict__ w_up,
                               const int* __restrict__ w_down_q) {
    int b = blockIdx.x;
    if (b < XB) {
        int i = b * 256 + threadIdx.x;
        float4 v = reinterpret_cast<const float4*>(x)[i];
        __half2* o = reinterpret_cast<__half2*>(g_xh);
        o[2 * i]     = __floats2half2_rn(v.x, v.y);
        o[2 * i + 1] = __floats2half2_rn(v.z, v.w);
    } else if (b < XB + WUPB) {
        int i = (b - XB) * 256 + threadIdx.x;
        float4 v = reinterpret_cast<const float4*>(w_up)[i];
        __half2* o = reinterpret_cast<__half2*>(g_wuph);
        o[2 * i]     = __floats2half2_rn(v.x, v.y);
        o[2 * i + 1] = __floats2half2_rn(v.z, v.w);
    } else {
        int i = (b - XB - WUPB) * 256 + threadIdx.x;
        int4 v = reinterpret_cast<const int4*>(w_down_q)[i];
        __half2* o = reinterpret_cast<__half2*>(g_wdh);
        o[2 * i]     = __floats2half2_rn((float)v.x, (float)v.y);
        o[2 * i + 1] = __floats2half2_rn((float)v.z, (float)v.w);
    }
}

// ---------------------------------------------------------------------------
// Tiled fp16 GEMM, fused epilogue, cross-tile pipelined mainloop (round-10):
//   Tile body:  loads(kt+2); ldsm1/mma0; ldsm2/mma1; ldsm3/mma0;
//               cp_wait; BAR; ldsm0'(kt+1); mma1.
// bias/scale tiles live in static smem (loaded pre-mainloop, published by
// the prologue barrier) so the epilogue has no exposed global loads.
// ---------------------------------------------------------------------------
template <int KDIM, int NDIM, bool IS_GEMM1>
__global__ void __launch_bounds__(NTHREADS, 2)
ffn_gemm_kernel(const float* __restrict__ bias,
                const float* __restrict__ scale,
                float* __restrict__ outp)
{
    extern __shared__ uint4 smem[];   // [STAGES][(BM+BN)*8] 16B chunks
    __shared__ float s_bias[BN];
    __shared__ float s_scale[BN];

    const __half* Ag = IS_GEMM1 ? g_xh   : g_h;
    const __half* Bg = IS_GEMM1 ? g_wuph : g_wdh;

    const int m0 = blockIdx.y * BM;
    const int n0 = blockIdx.x * BN;
    const int tid = threadIdx.x;
    const int wid = tid >> 5;
    const int lane = tid & 31;
    const int wm = (wid & 1) * 64;
    const int wn = (wid >> 1) * 64;

    float acc[4][8][4];
#pragma unroll
    for (int mt = 0; mt < 4; ++mt)
#pragma unroll
        for (int nt = 0; nt < 8; ++nt)
#pragma unroll
            for (int i = 0; i < 4; ++i) acc[mt][nt][i] = 0.0f;

    constexpr int KTILES = KDIM / BK;

    // ---- Hoisted per-thread load addressing ----
    const int rBase = tid >> 3;                  // row within tile, +16 per iter
    const int cIdx  = tid & 7;                   // 16B chunk column
    const int cSw   = cIdx ^ (rBase & 7);        // swizzled col (row-invariant +16)
    const __half* aSrc0 = Ag + (size_t)(m0 + rBase) * KDIM + cIdx * 8;
    const __half* bSrc0 = Bg + (size_t)(n0 + rBase) * KDIM + cIdx * 8;
    const int dstBase = rBase * 8 + cSw;

    auto load_stage = [&](int s, int kt) {
        const __half* aS = aSrc0 + kt * BK;
        const __half* bS = bSrc0 + kt * BK;
        uint4* Ad = smem + s * STAGE_CHUNKS + dstBase;
        uint4* Bd = Ad + A_CHUNKS;
#pragma unroll
        for (int i = 0; i < A_CHUNKS / NTHREADS; ++i)    // 8 iters
            cp_async16(smem_u32(Ad + i * 128), aS + (size_t)i * 16 * KDIM);
#pragma unroll
        for (int i = 0; i < B_CHUNKS / NTHREADS; ++i)    // 8 iters
            cp_async16(smem_u32(Bd + i * 128), bS + (size_t)i * 16 * KDIM);
    };

    // Fixed per-thread LDSM indices
    const int rowA0 = wm + (lane & 15);
    const int rowB0 = wn + ((lane >> 4) << 3) + (lane & 7);
    const int cA = (lane >> 4);
    const int cB = ((lane >> 3) & 1);

    uint32_t fA[2][4][4];
    uint32_t fB[2][4][4];

    auto ldsm_kk = [&](const uint4* Aa, const uint4* Ba, int kk, int buf) {
#pragma unroll
        for (int mt = 0; mt < 4; ++mt) {
            int row = rowA0 + mt * 16;
            int c = kk * 2 + cA;
            ldsm_x4(fA[buf][mt][0], fA[buf][mt][1], fA[buf][mt][2], fA[buf][mt][3],
                    smem_u32(Aa + row * 8 + (c ^ (row & 7))));
        }
#pragma unroll
        for (int nt2 = 0; nt2 < 4; ++nt2) {
            int row = rowB0 + nt2 * 16;
            int c = kk * 2 + cB;
            ldsm_x4(fB[buf][nt2][0], fB[buf][nt2][1], fB[buf][nt2][2], fB[buf][nt2][3],
                    smem_u32(Ba + row * 8 + (c ^ (row & 7))));
        }
    };

    auto mma_kk = [&](int buf) {
#pragma unroll
        for (int mt = 0; mt < 4; ++mt)
#pragma unroll
            for (int nt = 0; nt < 8; ++nt)
                mma16816(acc[mt][nt], fA[buf][mt], &fB[buf][nt >> 1][(nt & 1) * 2]);
    };

    // Prologue: fill STAGES-1 stages; also preload bias/scale tiles into smem
    // (published by the same barrier that publishes stage 0).
#pragma unroll
    for (int s = 0; s < STAGES - 1; ++s) {
        load_stage(s, s);
        cp_commit();
    }
    if (tid < BN) {                              // BN == NTHREADS == 128
        s_bias[tid] = bias[n0 + tid];
        s_scale[tid] = IS_GEMM1 ? 0.0f : scale[n0 + tid];
    }
    cp_wait<STAGES - 2>();   // own stage-0 group done
    __syncthreads();         // publishes ALL threads' stage-0 data (+ bias/scale)
    ldsm_kk(smem, smem + A_CHUNKS, 0, 0);

    for (int kt = 0; kt < KTILES; ++kt) {
        const uint4* Aa = smem + (kt % STAGES) * STAGE_CHUNKS;
        const uint4* Ba = Aa + A_CHUNKS;

        // Refill stage kt+2 (buffer freed by the barrier at end of tile kt-1).
        int ls = kt + STAGES - 1;
        if (ls < KTILES) load_stage(ls % STAGES, ls);
        cp_commit();   // unconditional: uniform group count

        ldsm_kk(Aa, Ba, 1, 1); mma_kk(0);
        ldsm_kk(Aa, Ba, 2, 0); mma_kk(1);
        ldsm_kk(Aa, Ba, 3, 1); mma_kk(0);

        // End-of-tile sync before the last MMA burst:
        cp_wait<STAGES - 2>();   // own stage-(kt+1) group done
        __syncthreads();         // all threads' stage-(kt+1) data published;
                                 // frees buffer (kt+2)%STAGES for next refill
        if (kt + 1 < KTILES) {
            const uint4* An = smem + ((kt + 1) % STAGES) * STAGE_CHUNKS;
            ldsm_kk(An, An + A_CHUNKS, 0, 0);   // prefetch next tile kk=0
        }
        mma_kk(1);               // independent of the prefetch -> no pipe gap
    }

    // ------------------------------------------------------------------ epilogue
    const int r0g = m0 + wm + (lane >> 2);
    const int lc0 = wn + ((lane & 3) << 1);      // local col in [0, BN)
    const int c0g = n0 + lc0;

    if (IS_GEMM1) {
#pragma unroll
        for (int mt = 0; mt < 4; ++mt)
#pragma unroll
            for (int hrow = 0; hrow < 2; ++hrow) {
                int row = r0g + mt * 16 + hrow * 8;
#pragma unroll
                for (int nt = 0; nt < 8; ++nt) {
                    int lc = lc0 + nt * 8;
                    float v0 = acc[mt][nt][hrow * 2]     + s_bias[lc];
                    float v1 = acc[mt][nt][hrow * 2 + 1] + s_bias[lc + 1];
                    v0 = gelu_exact(v0);
                    v1 = gelu_exact(v1);
                    *reinterpret_cast<__half2*>(&g_h[(size_t)row * NDIM + c0g + nt * 8]) =
                        __floats2half2_rn(v0, v1);
                }
            }
    } else {
#pragma unroll
        for (int mt = 0; mt < 4; ++mt)
#pragma unroll
            for (int hrow = 0; hrow < 2; ++hrow) {
                int row = r0g + mt * 16 + hrow * 8;
#pragma unroll
                for (int nt = 0; nt < 8; ++nt) {
                    int lc = lc0 + nt * 8;
                    float2 o;
                    o.x = acc[mt][nt][hrow * 2]     * s_scale[lc]     + s_bias[lc];
                    o.y = acc[mt][nt][hrow * 2 + 1] * s_scale[lc + 1] + s_bias[lc + 1];
                    *reinterpret_cast<float2*>(&outp[(size_t)row * NDIM + c0g + nt * 8]) = o;
                }
            }
    }
}

// ---------------------------------------------------------------------------
// Launch
// ---------------------------------------------------------------------------
extern "C" void kernel_launch(void* const* d_in, const int* in_sizes, int n_in,
                              void* d_out, int out_size)
{
    const float* x            = (const float*)d_in[0];  // [B,S,D]
    const float* w_up         = (const float*)d_in[1];  // [DI,D]
    const float* b_up         = (const float*)d_in[2];  // [DI]
    const int*   w_down_q     = (const int*)  d_in[3];  // [D,DI] int32
    const float* w_down_scale = (const float*)d_in[4];  // [D]
    const float* b_down       = (const float*)d_in[5];  // [D]
    float* out = (float*)d_out;                         // [B,S,D]

    cvt_all_kernel<<<XB + WUPB + WDB, 256>>>(x, w_up, w_down_q);

    cudaFuncSetAttribute(ffn_gemm_kernel<D_, DI_, true>,
                         cudaFuncAttributeMaxDynamicSharedMemorySize, SMEM_BYTES);
    ffn_gemm_kernel<D_, DI_, true>
        <<<dim3(DI_ / BN, MTOT / BM), NTHREADS, SMEM_BYTES>>>(b_up, nullptr, nullptr);

    cudaFuncSetAttribute(ffn_gemm_kernel<DI_, D_, false>,
                         cudaFuncAttributeMaxDynamicSharedMemorySize, SMEM_BYTES);
    ffn_gemm_kernel<DI_, D_, false>
        <<<dim3(D_ / BN, MTOT / BM), NTHREADS, SMEM_BYTES>>>(b_down, w_down_scale, out);
}

// round 13
// speedup vs baseline: 1.0686x; 1.0060x over previous
#include <cuda_runtime.h>
#include <cuda_fp16.h>
#include <cstdint>
#include <math.h>

// Problem dims (fixed by the dataset)
#define B_ 4
#define S_ 4096
#define D_ 2048
#define DI_ 8192
#define MTOT (B_ * S_)   // 16384

// ---------------------------------------------------------------------------
// Static device scratch
// ---------------------------------------------------------------------------
__device__ __half g_xh[(size_t)MTOT * D_];    //  64 MB  x in fp16
__device__ __half g_wuph[(size_t)DI_ * D_];   //  32 MB  w_up fp16 [DI, D] K-major
__device__ __half g_wdh[(size_t)D_ * DI_];    //  32 MB  w_down fp16 [D, DI] K-major
__device__ __half g_h[(size_t)MTOT * DI_];    // 256 MB  gelu(up) intermediate

// ---------------------------------------------------------------------------
// GEMM config: CTA 128x128, 4 warps (2M x 2N), warp tile 64x64, BK=64,
// 3 stages (96 KB), 2 CTAs/SM. Round-10 mainloop (best known).
// GEMM1 additionally performs the w_down int32->fp16 conversion after its
// epilogue (grid-strided), overlapping idle DRAM under other CTAs' mainloops.
// ---------------------------------------------------------------------------
constexpr int BM = 128;
constexpr int BN = 128;
constexpr int BK = 64;
constexpr int STAGES = 3;
constexpr int NTHREADS = 128;
constexpr int A_CHUNKS = BM * 8;
constexpr int B_CHUNKS = BN * 8;
constexpr int STAGE_CHUNKS = A_CHUNKS + B_CHUNKS;
constexpr int STAGE_BYTES = (BM + BN) * 128;     // 32 KB
constexpr int SMEM_BYTES = STAGES * STAGE_BYTES; // 96 KB dynamic

// ---------------------------------------------------------------------------
// PTX helpers
// ---------------------------------------------------------------------------
__device__ __forceinline__ uint32_t smem_u32(const void* p) {
    return (uint32_t)__cvta_generic_to_shared(p);
}
__device__ __forceinline__ void cp_async16(uint32_t dst, const void* src) {
    asm volatile("cp.async.cg.shared.global [%0], [%1], 16;\n"
                 :: "r"(dst), "l"(src) : "memory");
}
__device__ __forceinline__ void cp_commit() {
    asm volatile("cp.async.commit_group;\n" ::: "memory");
}
template <int N>
__device__ __forceinline__ void cp_wait() {
    asm volatile("cp.async.wait_group %0;\n" :: "n"(N) : "memory");
}
__device__ __forceinline__ void ldsm_x4(uint32_t& r0, uint32_t& r1, uint32_t& r2,
                                        uint32_t& r3, uint32_t addr) {
    asm volatile("ldmatrix.sync.aligned.m8n8.x4.shared.b16 {%0,%1,%2,%3}, [%4];\n"
                 : "=r"(r0), "=r"(r1), "=r"(r2), "=r"(r3) : "r"(addr));
}
__device__ __forceinline__ void mma16816(float* d, const uint32_t* a, const uint32_t* b) {
    asm volatile(
        "mma.sync.aligned.m16n8k16.row.col.f32.f16.f16.f32 "
        "{%0,%1,%2,%3}, {%4,%5,%6,%7}, {%8,%9}, {%0,%1,%2,%3};\n"
        : "+f"(d[0]), "+f"(d[1]), "+f"(d[2]), "+f"(d[3])
        : "r"(a[0]), "r"(a[1]), "r"(a[2]), "r"(a[3]), "r"(b[0]), "r"(b[1]));
}
__device__ __forceinline__ float gelu_exact(float v) {
    return 0.5f * v * (1.0f + erff(v * 0.70710678118654752f));
}

// ---------------------------------------------------------------------------
// Conversion kernel: x and w_up only (w_down handled inside GEMM1).
// ---------------------------------------------------------------------------
constexpr int XV   = (MTOT * D_) / 4;    // float4 groups
constexpr int WUPV = (DI_ * D_) / 4;
constexpr int XB   = XV / 256;
constexpr int WUPB = WUPV / 256;

__global__ void cvt_xw_kernel(const float* __restrict__ x,
                              const float* __restrict__ w_up) {
    int b = blockIdx.x;
    if (b < XB) {
        int i = b * 256 + threadIdx.x;
        float4 v = reinterpret_cast<const float4*>(x)[i];
        __half2* o = reinterpret_cast<__half2*>(g_xh);
        o[2 * i]     = __floats2half2_rn(v.x, v.y);
        o[2 * i + 1] = __floats2half2_rn(v.z, v.w);
    } else {
        int i = (b - XB) * 256 + threadIdx.x;
        float4 v = reinterpret_cast<const float4*>(w_up)[i];
        __half2* o = reinterpret_cast<__half2*>(g_wuph);
        o[2 * i]     = __floats2half2_rn(v.x, v.y);
        o[2 * i + 1] = __floats2half2_rn(v.z, v.w);
    }
}

// ---------------------------------------------------------------------------
// Tiled fp16 GEMM, fused epilogue, cross-tile pipelined mainloop (round-10):
//   Tile body:  loads(kt+2); ldsm1/mma0; ldsm2/mma1; ldsm3/mma0;
//               cp_wait; BAR; ldsm0'(kt+1); mma1.
// ---------------------------------------------------------------------------
template <int KDIM, int NDIM, bool IS_GEMM1>
__global__ void __launch_bounds__(NTHREADS, 2)
ffn_gemm_kernel(const float* __restrict__ bias,
                const float* __restrict__ scale,
                float* __restrict__ outp,
                const int* __restrict__ wdq)
{
    extern __shared__ uint4 smem[];   // [STAGES][(BM+BN)*8] 16B chunks
    __shared__ float s_bias[BN];
    __shared__ float s_scale[BN];

    const __half* Ag = IS_GEMM1 ? g_xh   : g_h;
    const __half* Bg = IS_GEMM1 ? g_wuph : g_wdh;

    const int m0 = blockIdx.y * BM;
    const int n0 = blockIdx.x * BN;
    const int tid = threadIdx.x;
    const int wid = tid >> 5;
    const int lane = tid & 31;
    const int wm = (wid & 1) * 64;
    const int wn = (wid >> 1) * 64;

    float acc[4][8][4];
#pragma unroll
    for (int mt = 0; mt < 4; ++mt)
#pragma unroll
        for (int nt = 0; nt < 8; ++nt)
#pragma unroll
            for (int i = 0; i < 4; ++i) acc[mt][nt][i] = 0.0f;

    constexpr int KTILES = KDIM / BK;

    // ---- Hoisted per-thread load addressing ----
    const int rBase = tid >> 3;
    const int cIdx  = tid & 7;
    const int cSw   = cIdx ^ (rBase & 7);
    const __half* aSrc0 = Ag + (size_t)(m0 + rBase) * KDIM + cIdx * 8;
    const __half* bSrc0 = Bg + (size_t)(n0 + rBase) * KDIM + cIdx * 8;
    const int dstBase = rBase * 8 + cSw;

    auto load_stage = [&](int s, int kt) {
        const __half* aS = aSrc0 + kt * BK;
        const __half* bS = bSrc0 + kt * BK;
        uint4* Ad = smem + s * STAGE_CHUNKS + dstBase;
        uint4* Bd = Ad + A_CHUNKS;
#pragma unroll
        for (int i = 0; i < A_CHUNKS / NTHREADS; ++i)
            cp_async16(smem_u32(Ad + i * 128), aS + (size_t)i * 16 * KDIM);
#pragma unroll
        for (int i = 0; i < B_CHUNKS / NTHREADS; ++i)
            cp_async16(smem_u32(Bd + i * 128), bS + (size_t)i * 16 * KDIM);
    };

    // Fixed per-thread LDSM indices
    const int rowA0 = wm + (lane & 15);
    const int rowB0 = wn + ((lane >> 4) << 3) + (lane & 7);
    const int cA = (lane >> 4);
    const int cB = ((lane >> 3) & 1);

    uint32_t fA[2][4][4];
    uint32_t fB[2][4][4];

    auto ldsm_kk = [&](const uint4* Aa, const uint4* Ba, int kk, int buf) {
#pragma unroll
        for (int mt = 0; mt < 4; ++mt) {
            int row = rowA0 + mt * 16;
            int c = kk * 2 + cA;
            ldsm_x4(fA[buf][mt][0], fA[buf][mt][1], fA[buf][mt][2], fA[buf][mt][3],
                    smem_u32(Aa + row * 8 + (c ^ (row & 7))));
        }
#pragma unroll
        for (int nt2 = 0; nt2 < 4; ++nt2) {
            int row = rowB0 + nt2 * 16;
            int c = kk * 2 + cB;
            ldsm_x4(fB[buf][nt2][0], fB[buf][nt2][1], fB[buf][nt2][2], fB[buf][nt2][3],
                    smem_u32(Ba + row * 8 + (c ^ (row & 7))));
        }
    };

    auto mma_kk = [&](int buf) {
#pragma unroll
        for (int mt = 0; mt < 4; ++mt)
#pragma unroll
            for (int nt = 0; nt < 8; ++nt)
                mma16816(acc[mt][nt], fA[buf][mt], &fB[buf][nt >> 1][(nt & 1) * 2]);
    };

    // Prologue: fill STAGES-1 stages; preload bias/scale tiles into smem.
#pragma unroll
    for (int s = 0; s < STAGES - 1; ++s) {
        load_stage(s, s);
        cp_commit();
    }
    if (tid < BN) {
        s_bias[tid] = bias[n0 + tid];
        s_scale[tid] = IS_GEMM1 ? 0.0f : scale[n0 + tid];
    }
    cp_wait<STAGES - 2>();
    __syncthreads();
    ldsm_kk(smem, smem + A_CHUNKS, 0, 0);

    for (int kt = 0; kt < KTILES; ++kt) {
        const uint4* Aa = smem + (kt % STAGES) * STAGE_CHUNKS;
        const uint4* Ba = Aa + A_CHUNKS;

        int ls = kt + STAGES - 1;
        if (ls < KTILES) load_stage(ls % STAGES, ls);
        cp_commit();

        ldsm_kk(Aa, Ba, 1, 1); mma_kk(0);
        ldsm_kk(Aa, Ba, 2, 0); mma_kk(1);
        ldsm_kk(Aa, Ba, 3, 1); mma_kk(0);

        cp_wait<STAGES - 2>();
        __syncthreads();
        if (kt + 1 < KTILES) {
            const uint4* An = smem + ((kt + 1) % STAGES) * STAGE_CHUNKS;
            ldsm_kk(An, An + A_CHUNKS, 0, 0);
        }
        mma_kk(1);
    }

    // ------------------------------------------------------------------ epilogue
    const int r0g = m0 + wm + (lane >> 2);
    const int lc0 = wn + ((lane & 3) << 1);
    const int c0g = n0 + lc0;

    if (IS_GEMM1) {
#pragma unroll
        for (int mt = 0; mt < 4; ++mt)
#pragma unroll
            for (int hrow = 0; hrow < 2; ++hrow) {
                int row = r0g + mt * 16 + hrow * 8;
#pragma unroll
                for (int nt = 0; nt < 8; ++nt) {
                    int lc = lc0 + nt * 8;
                    float v0 = acc[mt][nt][hrow * 2]     + s_bias[lc];
                    float v1 = acc[mt][nt][hrow * 2 + 1] + s_bias[lc + 1];
                    v0 = gelu_exact(v0);
                    v1 = gelu_exact(v1);
                    *reinterpret_cast<__half2*>(&g_h[(size_t)row * NDIM + c0g + nt * 8]) =
                        __floats2half2_rn(v0, v1);
                }
            }

        // ---- Folded w_down int32 -> fp16 conversion (grid-strided) ----
        // grid = 64 x 128 CTAs x 128 threads x 4 int4 x 4 elems = 2048*8192.
        {
            const int cta = blockIdx.y * gridDim.x + blockIdx.x;      // 0..8191
            const int base = cta * NTHREADS * 4 + tid;                // int4 index
            const int4* src = reinterpret_cast<const int4*>(wdq);
            __half2* dst = reinterpret_cast<__half2*>(g_wdh);
#pragma unroll
            for (int i = 0; i < 4; ++i) {
                int idx = base + i * NTHREADS;
                int4 v = src[idx];
                dst[2 * idx]     = __floats2half2_rn((float)v.x, (float)v.y);
                dst[2 * idx + 1] = __floats2half2_rn((float)v.z, (float)v.w);
            }
        }
    } else {
#pragma unroll
        for (int mt = 0; mt < 4; ++mt)
#pragma unroll
            for (int hrow = 0; hrow < 2; ++hrow) {
                int row = r0g + mt * 16 + hrow * 8;
#pragma unroll
                for (int nt = 0; nt < 8; ++nt) {
                    int lc = lc0 + nt * 8;
                    float2 o;
                    o.x = acc[mt][nt][hrow * 2]     * s_scale[lc]     + s_bias[lc];
                    o.y = acc[mt][nt][hrow * 2 + 1] * s_scale[lc + 1] + s_bias[lc + 1];
                    *reinterpret_cast<float2*>(&outp[(size_t)row * NDIM + c0g + nt * 8]) = o;
                }
            }
    }
}

// ---------------------------------------------------------------------------
// Launch
// ---------------------------------------------------------------------------
extern "C" void kernel_launch(void* const* d_in, const int* in_sizes, int n_in,
                              void* d_out, int out_size)
{
    const float* x            = (const float*)d_in[0];  // [B,S,D]
    const float* w_up         = (const float*)d_in[1];  // [DI,D]
    const float* b_up         = (const float*)d_in[2];  // [DI]
    const int*   w_down_q     = (const int*)  d_in[3];  // [D,DI] int32
    const float* w_down_scale = (const float*)d_in[4];  // [D]
    const float* b_down       = (const float*)d_in[5];  // [D]
    float* out = (float*)d_out;                         // [B,S,D]

    cvt_xw_kernel<<<XB + WUPB, 256>>>(x, w_up);

    cudaFuncSetAttribute(ffn_gemm_kernel<D_, DI_, true>,
                         cudaFuncAttributeMaxDynamicSharedMemorySize, SMEM_BYTES);
    ffn_gemm_kernel<D_, DI_, true>
        <<<dim3(DI_ / BN, MTOT / BM), NTHREADS, SMEM_BYTES>>>(b_up, nullptr, nullptr, w_down_q);

    cudaFuncSetAttribute(ffn_gemm_kernel<DI_, D_, false>,
                         cudaFuncAttributeMaxDynamicSharedMemorySize, SMEM_BYTES);
    ffn_gemm_kernel<DI_, D_, false>
        <<<dim3(D_ / BN, MTOT / BM), NTHREADS, SMEM_BYTES>>>(b_down, w_down_scale, out, nullptr);
}

// round 14
// speedup vs baseline: 1.0721x; 1.0033x over previous
#include <cuda_runtime.h>
#include <cuda_fp16.h>
#include <cstdint>
#include <math.h>

// Problem dims (fixed by the dataset)
#define B_ 4
#define S_ 4096
#define D_ 2048
#define DI_ 8192
#define MTOT (B_ * S_)   // 16384

// ---------------------------------------------------------------------------
// Static device scratch
// ---------------------------------------------------------------------------
__device__ __half g_xh[(size_t)MTOT * D_];    //  64 MB  x in fp16
__device__ __half g_wuph[(size_t)DI_ * D_];   //  32 MB  w_up fp16 [DI, D] K-major
__device__ __half g_wdh[(size_t)D_ * DI_];    //  32 MB  w_down fp16 [D, DI] K-major
__device__ __half g_h[(size_t)MTOT * DI_];    // 256 MB  gelu(up) intermediate

// ---------------------------------------------------------------------------
// GEMM config: CTA 128x128, 4 warps (2M x 2N), warp tile 64x64, BK=64,
// 3 stages (96 KB), 2 CTAs/SM. Round-10 mainloop (best known).
// GEMM1 folds the w_down int32->fp16 conversion into its epilogue.
// ---------------------------------------------------------------------------
constexpr int BM = 128;
constexpr int BN = 128;
constexpr int BK = 64;
constexpr int STAGES = 3;
constexpr int NTHREADS = 128;
constexpr int A_CHUNKS = BM * 8;
constexpr int B_CHUNKS = BN * 8;
constexpr int STAGE_CHUNKS = A_CHUNKS + B_CHUNKS;
constexpr int STAGE_BYTES = (BM + BN) * 128;     // 32 KB
constexpr int SMEM_BYTES = STAGES * STAGE_BYTES; // 96 KB dynamic

// ---------------------------------------------------------------------------
// PTX helpers
// ---------------------------------------------------------------------------
__device__ __forceinline__ uint32_t smem_u32(const void* p) {
    return (uint32_t)__cvta_generic_to_shared(p);
}
__device__ __forceinline__ void cp_async16(uint32_t dst, const void* src) {
    asm volatile("cp.async.cg.shared.global [%0], [%1], 16;\n"
                 :: "r"(dst), "l"(src) : "memory");
}
__device__ __forceinline__ void cp_commit() {
    asm volatile("cp.async.commit_group;\n" ::: "memory");
}
template <int N>
__device__ __forceinline__ void cp_wait() {
    asm volatile("cp.async.wait_group %0;\n" :: "n"(N) : "memory");
}
__device__ __forceinline__ void ldsm_x4(uint32_t& r0, uint32_t& r1, uint32_t& r2,
                                        uint32_t& r3, uint32_t addr) {
    asm volatile("ldmatrix.sync.aligned.m8n8.x4.shared.b16 {%0,%1,%2,%3}, [%4];\n"
                 : "=r"(r0), "=r"(r1), "=r"(r2), "=r"(r3) : "r"(addr));
}
__device__ __forceinline__ void mma16816(float* d, const uint32_t* a, const uint32_t* b) {
    asm volatile(
        "mma.sync.aligned.m16n8k16.row.col.f32.f16.f16.f32 "
        "{%0,%1,%2,%3}, {%4,%5,%6,%7}, {%8,%9}, {%0,%1,%2,%3};\n"
        : "+f"(d[0]), "+f"(d[1]), "+f"(d[2]), "+f"(d[3])
        : "r"(a[0]), "r"(a[1]), "r"(a[2]), "r"(a[3]), "r"(b[0]), "r"(b[1]));
}
__device__ __forceinline__ float gelu_exact(float v) {
    return 0.5f * v * (1.0f + erff(v * 0.70710678118654752f));
}

// ---------------------------------------------------------------------------
// Conversion kernel: x and w_up (w_down handled inside GEMM1).
// MLP=4: each thread front-batches 4 independent float4 loads (evict-first)
// then writes 8 half2 pairs. Block covers 1024 float4 groups.
// ---------------------------------------------------------------------------
constexpr int XV   = (MTOT * D_) / 4;    // float4 groups
constexpr int WUPV = (DI_ * D_) / 4;
constexpr int XB4  = XV / 1024;          // blocks covering x   (256 thr x 4)
constexpr int WUPB4 = WUPV / 1024;       // blocks covering w_up

__global__ void cvt_xw_kernel(const float* __restrict__ x,
                              const float* __restrict__ w_up) {
    int b = blockIdx.x;
    const float4* src;
    __half2* dst;
    int base;
    if (b < XB4) {
        src = reinterpret_cast<const float4*>(x);
        dst = reinterpret_cast<__half2*>(g_xh);
        base = b * 1024 + threadIdx.x;
    } else {
        src = reinterpret_cast<const float4*>(w_up);
        dst = reinterpret_cast<__half2*>(g_wuph);
        base = (b - XB4) * 1024 + threadIdx.x;
    }
    float4 v[4];
#pragma unroll
    for (int i = 0; i < 4; ++i)
        v[i] = __ldcs(&src[base + i * 256]);
#pragma unroll
    for (int i = 0; i < 4; ++i) {
        int idx = base + i * 256;
        dst[2 * idx]     = __floats2half2_rn(v[i].x, v[i].y);
        dst[2 * idx + 1] = __floats2half2_rn(v[i].z, v[i].w);
    }
}

// ---------------------------------------------------------------------------
// Tiled fp16 GEMM, fused epilogue, cross-tile pipelined mainloop (round-10):
//   Tile body:  loads(kt+2); ldsm1/mma0; ldsm2/mma1; ldsm3/mma0;
//               cp_wait; BAR; ldsm0'(kt+1); mma1.
// ---------------------------------------------------------------------------
template <int KDIM, int NDIM, bool IS_GEMM1>
__global__ void __launch_bounds__(NTHREADS, 2)
ffn_gemm_kernel(const float* __restrict__ bias,
                const float* __restrict__ scale,
                float* __restrict__ outp,
                const int* __restrict__ wdq)
{
    extern __shared__ uint4 smem[];   // [STAGES][(BM+BN)*8] 16B chunks
    __shared__ float s_bias[BN];
    __shared__ float s_scale[BN];

    const __half* Ag = IS_GEMM1 ? g_xh   : g_h;
    const __half* Bg = IS_GEMM1 ? g_wuph : g_wdh;

    const int m0 = blockIdx.y * BM;
    const int n0 = blockIdx.x * BN;
    const int tid = threadIdx.x;
    const int wid = tid >> 5;
    const int lane = tid & 31;
    const int wm = (wid & 1) * 64;
    const int wn = (wid >> 1) * 64;

    float acc[4][8][4];
#pragma unroll
    for (int mt = 0; mt < 4; ++mt)
#pragma unroll
        for (int nt = 0; nt < 8; ++nt)
#pragma unroll
            for (int i = 0; i < 4; ++i) acc[mt][nt][i] = 0.0f;

    constexpr int KTILES = KDIM / BK;

    // ---- Hoisted per-thread load addressing ----
    const int rBase = tid >> 3;
    const int cIdx  = tid & 7;
    const int cSw   = cIdx ^ (rBase & 7);
    const __half* aSrc0 = Ag + (size_t)(m0 + rBase) * KDIM + cIdx * 8;
    const __half* bSrc0 = Bg + (size_t)(n0 + rBase) * KDIM + cIdx * 8;
    const int dstBase = rBase * 8 + cSw;

    auto load_stage = [&](int s, int kt) {
        const __half* aS = aSrc0 + kt * BK;
        const __half* bS = bSrc0 + kt * BK;
        uint4* Ad = smem + s * STAGE_CHUNKS + dstBase;
        uint4* Bd = Ad + A_CHUNKS;
#pragma unroll
        for (int i = 0; i < A_CHUNKS / NTHREADS; ++i)
            cp_async16(smem_u32(Ad + i * 128), aS + (size_t)i * 16 * KDIM);
#pragma unroll
        for (int i = 0; i < B_CHUNKS / NTHREADS; ++i)
            cp_async16(smem_u32(Bd + i * 128), bS + (size_t)i * 16 * KDIM);
    };

    // Fixed per-thread LDSM indices
    const int rowA0 = wm + (lane & 15);
    const int rowB0 = wn + ((lane >> 4) << 3) + (lane & 7);
    const int cA = (lane >> 4);
    const int cB = ((lane >> 3) & 1);

    uint32_t fA[2][4][4];
    uint32_t fB[2][4][4];

    auto ldsm_kk = [&](const uint4* Aa, const uint4* Ba, int kk, int buf) {
#pragma unroll
        for (int mt = 0; mt < 4; ++mt) {
            int row = rowA0 + mt * 16;
            int c = kk * 2 + cA;
            ldsm_x4(fA[buf][mt][0], fA[buf][mt][1], fA[buf][mt][2], fA[buf][mt][3],
                    smem_u32(Aa + row * 8 + (c ^ (row & 7))));
        }
#pragma unroll
        for (int nt2 = 0; nt2 < 4; ++nt2) {
            int row = rowB0 + nt2 * 16;
            int c = kk * 2 + cB;
            ldsm_x4(fB[buf][nt2][0], fB[buf][nt2][1], fB[buf][nt2][2], fB[buf][nt2][3],
                    smem_u32(Ba + row * 8 + (c ^ (row & 7))));
        }
    };

    auto mma_kk = [&](int buf) {
#pragma unroll
        for (int mt = 0; mt < 4; ++mt)
#pragma unroll
            for (int nt = 0; nt < 8; ++nt)
                mma16816(acc[mt][nt], fA[buf][mt], &fB[buf][nt >> 1][(nt & 1) * 2]);
    };

    // Prologue: fill STAGES-1 stages; preload bias/scale tiles into smem.
#pragma unroll
    for (int s = 0; s < STAGES - 1; ++s) {
        load_stage(s, s);
        cp_commit();
    }
    if (tid < BN) {
        s_bias[tid] = bias[n0 + tid];
        s_scale[tid] = IS_GEMM1 ? 0.0f : scale[n0 + tid];
    }
    cp_wait<STAGES - 2>();
    __syncthreads();
    ldsm_kk(smem, smem + A_CHUNKS, 0, 0);

    for (int kt = 0; kt < KTILES; ++kt) {
        const uint4* Aa = smem + (kt % STAGES) * STAGE_CHUNKS;
        const uint4* Ba = Aa + A_CHUNKS;

        int ls = kt + STAGES - 1;
        if (ls < KTILES) load_stage(ls % STAGES, ls);
        cp_commit();

        ldsm_kk(Aa, Ba, 1, 1); mma_kk(0);
        ldsm_kk(Aa, Ba, 2, 0); mma_kk(1);
        ldsm_kk(Aa, Ba, 3, 1); mma_kk(0);

        cp_wait<STAGES - 2>();
        __syncthreads();
        if (kt + 1 < KTILES) {
            const uint4* An = smem + ((kt + 1) % STAGES) * STAGE_CHUNKS;
            ldsm_kk(An, An + A_CHUNKS, 0, 0);
        }
        mma_kk(1);
    }

    // ------------------------------------------------------------------ epilogue
    const int r0g = m0 + wm + (lane >> 2);
    const int lc0 = wn + ((lane & 3) << 1);
    const int c0g = n0 + lc0;

    if (IS_GEMM1) {
#pragma unroll
        for (int mt = 0; mt < 4; ++mt)
#pragma unroll
            for (int hrow = 0; hrow < 2; ++hrow) {
                int row = r0g + mt * 16 + hrow * 8;
#pragma unroll
                for (int nt = 0; nt < 8; ++nt) {
                    int lc = lc0 + nt * 8;
                    float v0 = acc[mt][nt][hrow * 2]     + s_bias[lc];
                    float v1 = acc[mt][nt][hrow * 2 + 1] + s_bias[lc + 1];
                    v0 = gelu_exact(v0);
                    v1 = gelu_exact(v1);
                    *reinterpret_cast<__half2*>(&g_h[(size_t)row * NDIM + c0g + nt * 8]) =
                        __floats2half2_rn(v0, v1);
                }
            }

        // ---- Folded w_down int32 -> fp16 conversion (grid-strided) ----
        {
            const int cta = blockIdx.y * gridDim.x + blockIdx.x;      // 0..8191
            const int base = cta * NTHREADS * 4 + tid;                // int4 index
            const int4* src = reinterpret_cast<const int4*>(wdq);
            __half2* dst = reinterpret_cast<__half2*>(g_wdh);
#pragma unroll
            for (int i = 0; i < 4; ++i) {
                int idx = base + i * NTHREADS;
                int4 v = __ldcs(&src[idx]);
                dst[2 * idx]     = __floats2half2_rn((float)v.x, (float)v.y);
                dst[2 * idx + 1] = __floats2half2_rn((float)v.z, (float)v.w);
            }
        }
    } else {
#pragma unroll
        for (int mt = 0; mt < 4; ++mt)
#pragma unroll
            for (int hrow = 0; hrow < 2; ++hrow) {
                int row = r0g + mt * 16 + hrow * 8;
#pragma unroll
                for (int nt = 0; nt < 8; ++nt) {
                    int lc = lc0 + nt * 8;
                    float2 o;
                    o.x = acc[mt][nt][hrow * 2]     * s_scale[lc]     + s_bias[lc];
                    o.y = acc[mt][nt][hrow * 2 + 1] * s_scale[lc + 1] + s_bias[lc + 1];
                    *reinterpret_cast<float2*>(&outp[(size_t)row * NDIM + c0g + nt * 8]) = o;
                }
            }
    }
}

// ---------------------------------------------------------------------------
// Launch
// ---------------------------------------------------------------------------
extern "C" void kernel_launch(void* const* d_in, const int* in_sizes, int n_in,
                              void* d_out, int out_size)
{
    const float* x            = (const float*)d_in[0];  // [B,S,D]
    const float* w_up         = (const float*)d_in[1];  // [DI,D]
    const float* b_up         = (const float*)d_in[2];  // [DI]
    const int*   w_down_q     = (const int*)  d_in[3];  // [D,DI] int32
    const float* w_down_scale = (const float*)d_in[4];  // [D]
    const float* b_down       = (const float*)d_in[5];  // [D]
    float* out = (float*)d_out;                         // [B,S,D]

    cvt_xw_kernel<<<XB4 + WUPB4, 256>>>(x, w_up);

    cudaFuncSetAttribute(ffn_gemm_kernel<D_, DI_, true>,
                         cudaFuncAttributeMaxDynamicSharedMemorySize, SMEM_BYTES);
    ffn_gemm_kernel<D_, DI_, true>
        <<<dim3(DI_ / BN, MTOT / BM), NTHREADS, SMEM_BYTES>>>(b_up, nullptr, nullptr, w_down_q);

    cudaFuncSetAttribute(ffn_gemm_kernel<DI_, D_, false>,
                         cudaFuncAttributeMaxDynamicSharedMemorySize, SMEM_BYTES);
    ffn_gemm_kernel<DI_, D_, false>
        <<<dim3(D_ / BN, MTOT / BM), NTHREADS, SMEM_BYTES>>>(b_down, w_down_scale, out, nullptr);
}